// round 7
// baseline (speedup 1.0000x reference)
#include <cuda_runtime.h>
#include <math.h>

// Problem dims
#define NR   512
#define DM   512
#define NH   8
#define HE   64
#define FF   2048
#define NL   6
#define MIX3 768

// ---------------- scratch (device globals; no allocation) ----------------
__device__ float g_h[NR * DM];
__device__ float g_q[NR * DM];
__device__ float g_k[NR * DM];
__device__ float g_v[NR * DM];
__device__ float g_attn[NR * DM];
__device__ float g_ffn[NR * FF];
__device__ float g_part[8 * NR * DM];   // split-K partials

// ---------------- embedding + positional concat ----------------
__global__ void embed_kernel(const int* __restrict__ x, const int* __restrict__ ip,
                             const float* __restrict__ emb, const float* __restrict__ pe) {
    int n = blockIdx.x;
    int d = threadIdx.x;
    int tok = x[n];
    int i   = ip[0];
    g_h[n * DM + d]       = emb[tok * 256 + d];
    g_h[n * DM + 256 + d] = pe[i * 256 + d];
}

// ---------------- TF32 tensor-core GEMM core ----------------
// Tile 64x64, BK=16, 256 threads = 8 warps (2m x 4n), warp tile 32x16.
// Depth-3 software pipeline: regs hold tiles kt+1, kt+2; smem double-buffered.
// A smem word: ((step*4 + blk16)*8 + g)*20 + (kq&3)*4 + half + 2*kh
// B smem word: (step*64 + n)*10 + bswz(k&3, n)*2 + kh

__device__ __forceinline__ unsigned f2tf32(float f) {
    unsigned u;
    asm("cvt.rna.tf32.f32 %0, %1;" : "=r"(u) : "f"(f));
    return u;
}

__device__ __forceinline__ int bswz(int tg, int n) {
    return (tg + (n >> 2) + (n >> 4)) & 3;
}

template <int ACT>
__device__ __forceinline__ void gemm_body(
    const float* __restrict__ A, const float* __restrict__ B,
    const float* __restrict__ bias, float* __restrict__ C,
    int N, int K, int kStart, int kEnd, int m0, int n0)
{
    __shared__ __align__(16) unsigned As[2][1280];
    __shared__ __align__(16) unsigned Bs[2][1280];

    const int t    = threadIdx.x;
    const int warp = t >> 5;
    const int lane = t & 31;
    const int g    = lane >> 2;
    const int tg   = lane & 3;
    const int wm   = warp >> 2;       // 0..1 -> m offset 32*wm
    const int wn   = warp & 3;        // 0..3 -> n offset 16*wn

    // A loader: row ar (0..63), k quad ak4
    const int ar    = t >> 2;
    const int ak4   = (t & 3) * 4;
    const int ablk  = ar >> 4;
    const int ag    = ar & 7;
    const int ahalf = (ar >> 3) & 1;
    // B loader: k row bk (0..15), n quad bn4
    const int bk  = t >> 4;
    const int bn4 = (t & 15) * 4;

    const float* Ap = A + (size_t)(m0 + ar) * K + kStart + ak4;
    const float* Bp = B + (size_t)(kStart + bk) * N + n0 + bn4;

    const int nt = (kEnd - kStart) >> 4;   // BK = 16

    float c[2][2][4];
#pragma unroll
    for (int i = 0; i < 2; i++)
#pragma unroll
        for (int j = 0; j < 2; j++)
#pragma unroll
            for (int r = 0; r < 4; r++) c[i][j][r] = 0.f;

#define ST_A(buf, v)                                                            \
    {                                                                           \
        const float va[4] = {(v).x, (v).y, (v).z, (v).w};                       \
        _Pragma("unroll")                                                       \
        for (int j = 0; j < 4; j++) {                                           \
            const int kq   = ak4 + j;                                           \
            const int step = kq >> 3;                                           \
            const int kh   = (kq >> 2) & 1;                                     \
            As[buf][((step * 4 + ablk) * 8 + ag) * 20 + (kq & 3) * 4 + ahalf + 2 * kh] \
                = f2tf32(va[j]);                                                \
        }                                                                       \
    }
#define ST_B(buf, v)                                                            \
    {                                                                           \
        const float vb[4] = {(v).x, (v).y, (v).z, (v).w};                       \
        const int step = bk >> 3;                                               \
        const int tgk  = bk & 3;                                                \
        const int kh   = (bk >> 2) & 1;                                         \
        _Pragma("unroll")                                                       \
        for (int j = 0; j < 4; j++) {                                           \
            const int n = bn4 + j;                                              \
            Bs[buf][(step * 64 + n) * 10 + bswz(tgk, n) * 2 + kh] = f2tf32(vb[j]); \
        }                                                                       \
    }

    // register pipeline: set s holds a future tile
    float4 aRg[2], bRg[2];
    aRg[0] = *(const float4*)Ap;
    bRg[0] = *(const float4*)Bp;
    if (nt > 1) {
        aRg[1] = *(const float4*)(Ap + 16);
        bRg[1] = *(const float4*)(Bp + (size_t)16 * N);
    }

    ST_A(0, aRg[0]);
    ST_B(0, bRg[0]);
    __syncthreads();

    for (int kt = 0; kt < nt; kt++) {
        const int cur = kt & 1;

        // prefetch tile kt+2 into regset cur (its old tile was stored last iter)
        if (kt + 2 < nt) {
            aRg[cur] = *(const float4*)(Ap + (size_t)(kt + 2) * 16);
            bRg[cur] = *(const float4*)(Bp + (size_t)(kt + 2) * 16 * N);
        }

#pragma unroll
        for (int step = 0; step < 2; step++) {
            uint4 af[2];
#pragma unroll
            for (int mt = 0; mt < 2; mt++)
                af[mt] = *(const uint4*)&As[cur][((step * 4 + wm * 2 + mt) * 8 + g) * 20 + tg * 4];
            uint2 bf[2];
#pragma unroll
            for (int ntl = 0; ntl < 2; ntl++) {
                const int col = wn * 16 + ntl * 8 + g;
                bf[ntl] = *(const uint2*)&Bs[cur][(step * 64 + col) * 10 + bswz(tg, col) * 2];
            }
#pragma unroll
            for (int mt = 0; mt < 2; mt++)
#pragma unroll
                for (int ntl = 0; ntl < 2; ntl++) {
                    asm volatile(
                        "mma.sync.aligned.m16n8k8.row.col.f32.tf32.tf32.f32 "
                        "{%0,%1,%2,%3}, {%4,%5,%6,%7}, {%8,%9}, {%0,%1,%2,%3};"
                        : "+f"(c[mt][ntl][0]), "+f"(c[mt][ntl][1]),
                          "+f"(c[mt][ntl][2]), "+f"(c[mt][ntl][3])
                        : "r"(af[mt].x), "r"(af[mt].y), "r"(af[mt].z), "r"(af[mt].w),
                          "r"(bf[ntl].x), "r"(bf[ntl].y));
                }
        }

        // store tile kt+1 (in regset cur^1) into the spare buffer
        if (kt + 1 < nt) {
            const int nx = cur ^ 1;
            ST_A(nx, aRg[nx]);
            ST_B(nx, bRg[nx]);
        }
        __syncthreads();
    }
#undef ST_A
#undef ST_B

    // epilogue: rows g/g+8, cols tg*2, tg*2+1
#pragma unroll
    for (int mt = 0; mt < 2; mt++) {
#pragma unroll
        for (int ntl = 0; ntl < 2; ntl++) {
#pragma unroll
            for (int half = 0; half < 2; half++) {
                const int row = m0 + wm * 32 + mt * 16 + g + half * 8;
                const int col = n0 + wn * 16 + ntl * 8 + tg * 2;
                float v0 = c[mt][ntl][half * 2 + 0];
                float v1 = c[mt][ntl][half * 2 + 1];
                if (bias) { v0 += bias[col]; v1 += bias[col + 1]; }
                if (ACT == 1) {
                    v0 = (v0 > 0.f) ? (v0 + 1.f) : __expf(v0);
                    v1 = (v1 > 0.f) ? (v1 + 1.f) : __expf(v1);
                }
                if (ACT == 2) { v0 = fmaxf(v0, 0.f); v1 = fmaxf(v1, 0.f); }
                float2 o = make_float2(v0, v1);
                *(float2*)&C[(size_t)row * N + col] = o;
            }
        }
    }
}

// Plain GEMM (full K); tile 64x64
template <int ACT>
__global__ __launch_bounds__(256, 2) void gemm_kernel(
    const float* __restrict__ A, const float* __restrict__ B,
    const float* __restrict__ bias, float* __restrict__ C, int N, int K)
{
    gemm_body<ACT>(A, B, bias, C, N, K, 0, K, blockIdx.y * 64, blockIdx.x * 64);
}

// Split-K GEMM: partials to Cp + z*NR*N
__global__ __launch_bounds__(256, 2) void gemm_splitk_kernel(
    const float* __restrict__ A, const float* __restrict__ B,
    float* __restrict__ Cp, int N, int K, int S)
{
    const int chunk = K / S;
    const int z = blockIdx.z;
    gemm_body<0>(A, B, nullptr, Cp + (size_t)z * NR * N,
                 N, K, z * chunk, (z + 1) * chunk, blockIdx.y * 64, blockIdx.x * 64);
}

// Fused QKV
__global__ __launch_bounds__(256, 2) void gemm_qkv_kernel(
    const float* __restrict__ h,
    const float* __restrict__ Wq, const float* __restrict__ Wk, const float* __restrict__ Wv,
    const float* __restrict__ bq, const float* __restrict__ bk, const float* __restrict__ bv,
    float* __restrict__ q, float* __restrict__ k, float* __restrict__ v, int l)
{
    const size_t w = (size_t)l * DM * DM;
    const int m0 = blockIdx.y * 64, n0 = blockIdx.x * 64;
    if (blockIdx.z == 0)
        gemm_body<1>(h, Wq + w, bq + l * DM, q, DM, DM, 0, DM, m0, n0);
    else if (blockIdx.z == 1)
        gemm_body<1>(h, Wk + w, bk + l * DM, k, DM, DM, 0, DM, m0, n0);
    else
        gemm_body<0>(h, Wv + w, bv + l * DM, v, DM, DM, 0, DM, m0, n0);
}

// ---------------- split-K reduce + bias (pred head) ----------------
__global__ void reduce_bias_kernel(const float* __restrict__ part, int P,
                                   const float* __restrict__ bias,
                                   float* __restrict__ outp, int N)
{
    const int n = blockIdx.x;
    for (int c = threadIdx.x; c < N; c += blockDim.x) {
        float v = bias[c];
        for (int p = 0; p < P; p++)
            v += part[(size_t)p * NR * N + (size_t)n * N + c];
        outp[(size_t)n * N + c] = v;
    }
}

// ---------------- linear-attention state update + readout ----------------
__global__ void attn_kernel(const float* __restrict__ Q, const float* __restrict__ Kmat,
                            const float* __restrict__ V,
                            const float* __restrict__ Si, const float* __restrict__ Zi,
                            float* __restrict__ S_out, float* __restrict__ Z_out,
                            float* __restrict__ attn)
{
    const int n = blockIdx.x;
    const int h = blockIdx.y;
    const int m = threadIdx.x;

    __shared__ float qs[HE], ks[HE], red[HE];

    const int baseqk = n * DM + h * HE;
    qs[m] = Q[baseqk + m];
    ks[m] = Kmat[baseqk + m];
    const float vm = V[baseqk + m];

    const size_t zbase = ((size_t)n * NH + h) * HE;
    const float z = Zi[zbase + m] + ks[m];
    Z_out[zbase + m] = z;

    red[m] = qs[m] * z;
    __syncthreads();
#pragma unroll
    for (int s = 32; s > 0; s >>= 1) {
        if (m < s) red[m] += red[m + s];
        __syncthreads();
    }
    const float den = red[0] + 1e-6f;

    const size_t sbase = ((size_t)n * NH + h) * HE * HE;
    float num = 0.f;
#pragma unroll 8
    for (int e = 0; e < HE; e++) {
        float s = Si[sbase + (size_t)e * HE + m] + ks[e] * vm;
        S_out[sbase + (size_t)e * HE + m] = s;
        num = fmaf(qs[e], s, num);
    }
    attn[baseqk + m] = num / den;
}

// ---------------- residual + split-K reduce + bias + LayerNorm -----------
__global__ void add_ln_kernel(float* __restrict__ hbuf, const float* __restrict__ part,
                              int P, const float* __restrict__ bias,
                              const float* __restrict__ g, const float* __restrict__ b)
{
    const int n = blockIdx.x;
    const int t = threadIdx.x;
    __shared__ float red[256];
    __shared__ float s_mean, s_rstd;

    float v0 = hbuf[n * DM + t];
    float v1 = hbuf[n * DM + 256 + t];
    for (int p = 0; p < P; p++) {
        v0 += part[(size_t)p * NR * DM + n * DM + t];
        v1 += part[(size_t)p * NR * DM + n * DM + 256 + t];
    }
    if (bias) { v0 += bias[t]; v1 += bias[256 + t]; }

    red[t] = v0 + v1;
    __syncthreads();
#pragma unroll
    for (int s = 128; s > 0; s >>= 1) {
        if (t < s) red[t] += red[t + s];
        __syncthreads();
    }
    if (t == 0) s_mean = red[0] * (1.f / DM);
    __syncthreads();
    const float mean = s_mean;

    float d0 = v0 - mean, d1 = v1 - mean;
    red[t] = d0 * d0 + d1 * d1;
    __syncthreads();
#pragma unroll
    for (int s = 128; s > 0; s >>= 1) {
        if (t < s) red[t] += red[t + s];
        __syncthreads();
    }
    if (t == 0) s_rstd = rsqrtf(red[0] * (1.f / DM) + 1e-5f);
    __syncthreads();
    const float rstd = s_rstd;

    hbuf[n * DM + t]       = d0 * rstd * g[t]       + b[t];
    hbuf[n * DM + 256 + t] = d1 * rstd * g[256 + t] + b[256 + t];
}

// ---------------- host-side launch ----------------
extern "C" void kernel_launch(void* const* d_in, const int* in_sizes, int n_in,
                              void* d_out, int out_size)
{
    const int*   x      = (const int*)  d_in[0];
    const int*   ip     = (const int*)  d_in[1];
    const float* emb    = (const float*)d_in[2];
    const float* pe     = (const float*)d_in[3];
    const float* Wq     = (const float*)d_in[4];
    const float* bq     = (const float*)d_in[5];
    const float* Wk     = (const float*)d_in[6];
    const float* bk     = (const float*)d_in[7];
    const float* Wv     = (const float*)d_in[8];
    const float* bv     = (const float*)d_in[9];
    const float* Wo     = (const float*)d_in[10];
    const float* bo     = (const float*)d_in[11];
    const float* ln1_g  = (const float*)d_in[12];
    const float* ln1_b  = (const float*)d_in[13];
    const float* lin1_w = (const float*)d_in[14];
    const float* lin1_b = (const float*)d_in[15];
    const float* lin2_w = (const float*)d_in[16];
    const float* lin2_b = (const float*)d_in[17];
    const float* ln2_g  = (const float*)d_in[18];
    const float* ln2_b  = (const float*)d_in[19];
    const float* lnf_g  = (const float*)d_in[20];
    const float* lnf_b  = (const float*)d_in[21];
    const float* pred_w = (const float*)d_in[22];
    const float* pred_b = (const float*)d_in[23];
    const float* Si     = (const float*)d_in[24];
    const float* Zi     = (const float*)d_in[25];

    float* out = (float*)d_out;
    float* out_yhat = out;
    float* out_S    = out + (size_t)NR * MIX3;
    float* out_Z    = out_S + (size_t)NL * NR * NH * HE * HE;

    float *h, *q, *k, *v, *attn, *ffn, *part;
    cudaGetSymbolAddress((void**)&h,    g_h);
    cudaGetSymbolAddress((void**)&q,    g_q);
    cudaGetSymbolAddress((void**)&k,    g_k);
    cudaGetSymbolAddress((void**)&v,    g_v);
    cudaGetSymbolAddress((void**)&attn, g_attn);
    cudaGetSymbolAddress((void**)&ffn,  g_ffn);
    cudaGetSymbolAddress((void**)&part, g_part);

    embed_kernel<<<NR, 256>>>(x, ip, emb, pe);

    const dim3 gQKV(DM / 64, NR / 64, 3);      // 192 blocks
    const dim3 gWo(DM / 64, NR / 64, 4);       // 256 blocks (split-K 4)
    const dim3 gF1(FF / 64, NR / 64);          // 256 blocks
    const dim3 gF2(DM / 64, NR / 64, 4);       // 256 blocks (split-K 4, chunk 512)
    const dim3 gPred(MIX3 / 64, NR / 64, 4);   // 384 blocks (split-K 4)
    const dim3 gAttn(NR, NH);

    const size_t ssz = (size_t)NR * NH * HE * HE;
    const size_t zsz = (size_t)NR * NH * HE;

    for (int l = 0; l < NL; l++) {
        gemm_qkv_kernel<<<gQKV, 256>>>(h, Wq, Wk, Wv, bq, bk, bv, q, k, v, l);

        attn_kernel<<<gAttn, HE>>>(q, k, v, Si + l * ssz, Zi + l * zsz,
                                   out_S + l * ssz, out_Z + l * zsz, attn);

        gemm_splitk_kernel<<<gWo, 256>>>(attn, Wo + (size_t)l * DM * DM, part, DM, DM, 4);
        add_ln_kernel<<<NR, 256>>>(h, part, 4, bo + l * DM, ln1_g + l * DM, ln1_b + l * DM);

        gemm_kernel<2><<<gF1, 256>>>(h, lin1_w + (size_t)l * DM * FF, lin1_b + l * FF,
                                     ffn, FF, DM);
        gemm_splitk_kernel<<<gF2, 256>>>(ffn, lin2_w + (size_t)l * FF * DM, part, DM, FF, 4);
        add_ln_kernel<<<NR, 256>>>(h, part, 4, lin2_b + l * DM, ln2_g + l * DM, ln2_b + l * DM);
    }

    add_ln_kernel<<<NR, 256>>>(h, (const float*)nullptr, 0, (const float*)nullptr, lnf_g, lnf_b);
    gemm_splitk_kernel<<<gPred, 256>>>(h, pred_w, part, MIX3, DM, 4);
    reduce_bias_kernel<<<NR, 256>>>(part, 4, pred_b, out_yhat, MIX3);
}

// round 9
// speedup vs baseline: 1.2897x; 1.2897x over previous
#include <cuda_runtime.h>
#include <math.h>

// Problem dims
#define NR   512
#define DM   512
#define NH   8
#define HE   64
#define FF   2048
#define NL   6
#define MIX3 768

// ---------------- scratch (device globals; no allocation) ----------------
__device__ float g_h[NR * DM];
__device__ float g_attn[NR * DM];
__device__ float g_ffn[NR * FF];
__device__ float g_part[6 * NR * DM];   // split-K partials (6*512*512 = 4*512*768)

// ---------------- embedding + positional concat ----------------
__global__ void embed_kernel(const int* __restrict__ x, const int* __restrict__ ip,
                             const float* __restrict__ emb, const float* __restrict__ pe) {
    int n = blockIdx.x;
    int d = threadIdx.x;
    int tok = x[n];
    int i   = ip[0];
    g_h[n * DM + d]       = emb[tok * 256 + d];
    g_h[n * DM + 256 + d] = pe[i * 256 + d];
}

// ---------------- TF32 tensor-core GEMM core (R5-validated) ----------------
// Tile 64x64, BK=16, 256 threads = 8 warps (2m x 4n), warp tile 32x16.
// A smem word: ((step*4 + blk16)*8 + g)*20 + (kq&3)*4 + half + 2*kh
// B smem word: (step*64 + n)*10 + bswz(k&3, n)*2 + kh

__device__ __forceinline__ unsigned f2tf32(float f) {
    unsigned u;
    asm("cvt.rna.tf32.f32 %0, %1;" : "=r"(u) : "f"(f));
    return u;
}

__device__ __forceinline__ int bswz(int tg, int n) {
    return (tg + (n >> 2) + (n >> 4)) & 3;
}

template <int ACT>
__device__ __forceinline__ void gemm_body(
    const float* __restrict__ A, const float* __restrict__ B,
    const float* __restrict__ bias, float* __restrict__ C,
    int N, int K, int kStart, int kEnd, int m0, int n0)
{
    __shared__ __align__(16) unsigned As[2][2560];
    __shared__ __align__(16) unsigned Bs[2][2560];

    const int t    = threadIdx.x;
    const int warp = t >> 5;
    const int lane = t & 31;
    const int g    = lane >> 2;
    const int tg   = lane & 3;
    const int wm   = warp >> 2;       // 0..1 -> m offset 32*wm
    const int wn   = warp & 3;        // 0..3 -> n offset 16*wn

    // A loader: row ar, k quads ak4 and ak4+16
    const int ar    = t >> 2;         // 0..63
    const int ak4   = (t & 3) * 4;    // 0,4,8,12
    const int ablk  = ar >> 4;
    const int ag    = ar & 7;
    const int ahalf = (ar >> 3) & 1;
    // B loader: k rows bk and bk+16, n quad bn4
    const int bk  = t >> 4;           // 0..15
    const int bn4 = (t & 15) * 4;

    const float* Ap = A + (size_t)(m0 + ar) * K + kStart + ak4;
    const float* Bp = B + (size_t)(kStart + bk) * N + n0 + bn4;

    const int nt = (kEnd - kStart) >> 5;   // BK = 32

    float c[2][2][4];
#pragma unroll
    for (int i = 0; i < 2; i++)
#pragma unroll
        for (int j = 0; j < 2; j++)
#pragma unroll
            for (int r = 0; r < 4; r++) c[i][j][r] = 0.f;

#define ST_A(buf, kkbase, v)                                                  \
    {                                                                         \
        const float va[4] = {(v).x, (v).y, (v).z, (v).w};                     \
        _Pragma("unroll")                                                     \
        for (int j = 0; j < 4; j++) {                                         \
            const int kq   = (kkbase) + j;                                    \
            const int step = kq >> 3;                                         \
            const int kh   = (kq >> 2) & 1;                                   \
            As[buf][((step * 4 + ablk) * 8 + ag) * 20 + (kq & 3) * 4 + ahalf + 2 * kh] \
                = f2tf32(va[j]);                                              \
        }                                                                     \
    }
#define ST_B(buf, kk, v)                                                      \
    {                                                                         \
        const float vb[4] = {(v).x, (v).y, (v).z, (v).w};                     \
        const int step = (kk) >> 3;                                           \
        const int tgk  = (kk) & 3;                                            \
        const int kh   = ((kk) >> 2) & 1;                                     \
        _Pragma("unroll")                                                     \
        for (int j = 0; j < 4; j++) {                                         \
            const int n = bn4 + j;                                            \
            Bs[buf][(step * 64 + n) * 10 + bswz(tgk, n) * 2 + kh] = f2tf32(vb[j]); \
        }                                                                     \
    }

    float4 aR0 = *(const float4*)Ap;
    float4 aR1 = *(const float4*)(Ap + 16);
    float4 bR0 = *(const float4*)Bp;
    float4 bR1 = *(const float4*)(Bp + (size_t)16 * N);

    ST_A(0, ak4, aR0);
    ST_A(0, ak4 + 16, aR1);
    ST_B(0, bk, bR0);
    ST_B(0, bk + 16, bR1);
    __syncthreads();

    for (int kt = 0; kt < nt; kt++) {
        const int cur = kt & 1;
        if (kt + 1 < nt) {
            const float* Ap2 = Ap + (kt + 1) * 32;
            const float* Bp2 = Bp + (size_t)(kt + 1) * 32 * N;
            aR0 = *(const float4*)Ap2;
            aR1 = *(const float4*)(Ap2 + 16);
            bR0 = *(const float4*)Bp2;
            bR1 = *(const float4*)(Bp2 + (size_t)16 * N);
        }

#pragma unroll
        for (int step = 0; step < 4; step++) {
            uint4 af[2];
#pragma unroll
            for (int mt = 0; mt < 2; mt++)
                af[mt] = *(const uint4*)&As[cur][((step * 4 + wm * 2 + mt) * 8 + g) * 20 + tg * 4];
            uint2 bf[2];
#pragma unroll
            for (int ntl = 0; ntl < 2; ntl++) {
                const int col = wn * 16 + ntl * 8 + g;
                bf[ntl] = *(const uint2*)&Bs[cur][(step * 64 + col) * 10 + bswz(tg, col) * 2];
            }
#pragma unroll
            for (int mt = 0; mt < 2; mt++)
#pragma unroll
                for (int ntl = 0; ntl < 2; ntl++) {
                    asm volatile(
                        "mma.sync.aligned.m16n8k8.row.col.f32.tf32.tf32.f32 "
                        "{%0,%1,%2,%3}, {%4,%5,%6,%7}, {%8,%9}, {%0,%1,%2,%3};"
                        : "+f"(c[mt][ntl][0]), "+f"(c[mt][ntl][1]),
                          "+f"(c[mt][ntl][2]), "+f"(c[mt][ntl][3])
                        : "r"(af[mt].x), "r"(af[mt].y), "r"(af[mt].z), "r"(af[mt].w),
                          "r"(bf[ntl].x), "r"(bf[ntl].y));
                }
        }

        if (kt + 1 < nt) {
            const int nx = cur ^ 1;
            ST_A(nx, ak4, aR0);
            ST_A(nx, ak4 + 16, aR1);
            ST_B(nx, bk, bR0);
            ST_B(nx, bk + 16, bR1);
        }
        __syncthreads();
    }
#undef ST_A
#undef ST_B

    // epilogue: rows g/g+8, cols tg*2, tg*2+1
#pragma unroll
    for (int mt = 0; mt < 2; mt++) {
#pragma unroll
        for (int ntl = 0; ntl < 2; ntl++) {
#pragma unroll
            for (int half = 0; half < 2; half++) {
                const int row = m0 + wm * 32 + mt * 16 + g + half * 8;
                const int col = n0 + wn * 16 + ntl * 8 + tg * 2;
                float v0 = c[mt][ntl][half * 2 + 0];
                float v1 = c[mt][ntl][half * 2 + 1];
                if (bias) { v0 += bias[col]; v1 += bias[col + 1]; }
                if (ACT == 1) {
                    v0 = (v0 > 0.f) ? (v0 + 1.f) : __expf(v0);
                    v1 = (v1 > 0.f) ? (v1 + 1.f) : __expf(v1);
                }
                if (ACT == 2) { v0 = fmaxf(v0, 0.f); v1 = fmaxf(v1, 0.f); }
                float2 o = make_float2(v0, v1);
                *(float2*)&C[(size_t)row * N + col] = o;
            }
        }
    }
}

// Plain GEMM (full K); tile 64x64
template <int ACT>
__global__ __launch_bounds__(256, 2) void gemm_kernel(
    const float* __restrict__ A, const float* __restrict__ B,
    const float* __restrict__ bias, float* __restrict__ C, int N, int K)
{
    gemm_body<ACT>(A, B, bias, C, N, K, 0, K, blockIdx.y * 64, blockIdx.x * 64);
}

// Split-K GEMM: partials to Cp + z*NR*N
__global__ __launch_bounds__(256, 2) void gemm_splitk_kernel(
    const float* __restrict__ A, const float* __restrict__ B,
    float* __restrict__ Cp, int N, int K, int S)
{
    const int chunk = K / S;
    const int z = blockIdx.z;
    gemm_body<0>(A, B, nullptr, Cp + (size_t)z * NR * N,
                 N, K, z * chunk, (z + 1) * chunk, blockIdx.y * 64, blockIdx.x * 64);
}

// Fused QKV with split-K 2: z = which*2 + chunk, which: 0=Q 1=K 2=V
// Partials (no bias/phi — deferred to attn_kernel).
__global__ __launch_bounds__(256, 2) void gemm_qkv_splitk_kernel(
    const float* __restrict__ h,
    const float* __restrict__ Wq, const float* __restrict__ Wk, const float* __restrict__ Wv,
    float* __restrict__ part, int l)
{
    const int z = blockIdx.z;
    const int which = z >> 1;
    const int chunk = z & 1;
    const float* W = ((which == 0) ? Wq : (which == 1) ? Wk : Wv) + (size_t)l * DM * DM;
    gemm_body<0>(h, W, nullptr, part + (size_t)z * NR * DM,
                 DM, DM, chunk * 256, (chunk + 1) * 256, blockIdx.y * 64, blockIdx.x * 64);
}

// ---------------- split-K reduce + bias (pred head) ----------------
__global__ void reduce_bias_kernel(const float* __restrict__ part, int P,
                                   const float* __restrict__ bias,
                                   float* __restrict__ outp, int N)
{
    const int n = blockIdx.x;
    for (int c = threadIdx.x; c < N; c += blockDim.x) {
        float v = bias[c];
        for (int p = 0; p < P; p++)
            v += part[(size_t)p * NR * N + (size_t)n * N + c];
        outp[(size_t)n * N + c] = v;
    }
}

// ---------------- linear-attention: QKV reduce+bias+phi, state update ------
// part layout: z=0,1 Q partials; 2,3 K partials; 4,5 V partials
__global__ void attn_kernel(const float* __restrict__ part,
                            const float* __restrict__ bq, const float* __restrict__ bk,
                            const float* __restrict__ bv, int l,
                            const float* __restrict__ Si, const float* __restrict__ Zi,
                            float* __restrict__ S_out, float* __restrict__ Z_out,
                            float* __restrict__ attn)
{
    const int n = blockIdx.x;
    const int h = blockIdx.y;
    const int m = threadIdx.x;

    __shared__ float qs[HE], ks[HE], red[HE];

    const int baseqk = n * DM + h * HE;
    const size_t psz = (size_t)NR * DM;

    float qv = part[baseqk + m] + part[psz + baseqk + m] + bq[l * DM + h * HE + m];
    float kv = part[2 * psz + baseqk + m] + part[3 * psz + baseqk + m] + bk[l * DM + h * HE + m];
    const float vm = part[4 * psz + baseqk + m] + part[5 * psz + baseqk + m] + bv[l * DM + h * HE + m];

    qs[m] = (qv > 0.f) ? (qv + 1.f) : __expf(qv);
    ks[m] = (kv > 0.f) ? (kv + 1.f) : __expf(kv);

    const size_t zbase = ((size_t)n * NH + h) * HE;
    const float z = Zi[zbase + m] + ks[m];
    Z_out[zbase + m] = z;

    red[m] = qs[m] * z;
    __syncthreads();
#pragma unroll
    for (int s = 32; s > 0; s >>= 1) {
        if (m < s) red[m] += red[m + s];
        __syncthreads();
    }
    const float den = red[0] + 1e-6f;

    const size_t sbase = ((size_t)n * NH + h) * HE * HE;
    float num = 0.f;
#pragma unroll 8
    for (int e = 0; e < HE; e++) {
        float s = Si[sbase + (size_t)e * HE + m] + ks[e] * vm;
        S_out[sbase + (size_t)e * HE + m] = s;
        num = fmaf(qs[e], s, num);
    }
    attn[baseqk + m] = num / den;
}

// ---------------- residual + split-K reduce + bias + LayerNorm -----------
__global__ void add_ln_kernel(float* __restrict__ hbuf, const float* __restrict__ part,
                              int P, const float* __restrict__ bias,
                              const float* __restrict__ g, const float* __restrict__ b)
{
    const int n = blockIdx.x;
    const int t = threadIdx.x;
    __shared__ float red[256];
    __shared__ float s_mean, s_rstd;

    float v0 = hbuf[n * DM + t];
    float v1 = hbuf[n * DM + 256 + t];
    for (int p = 0; p < P; p++) {
        v0 += part[(size_t)p * NR * DM + n * DM + t];
        v1 += part[(size_t)p * NR * DM + n * DM + 256 + t];
    }
    if (bias) { v0 += bias[t]; v1 += bias[256 + t]; }

    red[t] = v0 + v1;
    __syncthreads();
#pragma unroll
    for (int s = 128; s > 0; s >>= 1) {
        if (t < s) red[t] += red[t + s];
        __syncthreads();
    }
    if (t == 0) s_mean = red[0] * (1.f / DM);
    __syncthreads();
    const float mean = s_mean;

    float d0 = v0 - mean, d1 = v1 - mean;
    red[t] = d0 * d0 + d1 * d1;
    __syncthreads();
#pragma unroll
    for (int s = 128; s > 0; s >>= 1) {
        if (t < s) red[t] += red[t + s];
        __syncthreads();
    }
    if (t == 0) s_rstd = rsqrtf(red[0] * (1.f / DM) + 1e-5f);
    __syncthreads();
    const float rstd = s_rstd;

    hbuf[n * DM + t]       = d0 * rstd * g[t]       + b[t];
    hbuf[n * DM + 256 + t] = d1 * rstd * g[256 + t] + b[256 + t];
}

// ---------------- host-side launch ----------------
extern "C" void kernel_launch(void* const* d_in, const int* in_sizes, int n_in,
                              void* d_out, int out_size)
{
    const int*   x      = (const int*)  d_in[0];
    const int*   ip     = (const int*)  d_in[1];
    const float* emb    = (const float*)d_in[2];
    const float* pe     = (const float*)d_in[3];
    const float* Wq     = (const float*)d_in[4];
    const float* bq     = (const float*)d_in[5];
    const float* Wk     = (const float*)d_in[6];
    const float* bk     = (const float*)d_in[7];
    const float* Wv     = (const float*)d_in[8];
    const float* bv     = (const float*)d_in[9];
    const float* Wo     = (const float*)d_in[10];
    const float* bo     = (const float*)d_in[11];
    const float* ln1_g  = (const float*)d_in[12];
    const float* ln1_b  = (const float*)d_in[13];
    const float* lin1_w = (const float*)d_in[14];
    const float* lin1_b = (const float*)d_in[15];
    const float* lin2_w = (const float*)d_in[16];
    const float* lin2_b = (const float*)d_in[17];
    const float* ln2_g  = (const float*)d_in[18];
    const float* ln2_b  = (const float*)d_in[19];
    const float* lnf_g  = (const float*)d_in[20];
    const float* lnf_b  = (const float*)d_in[21];
    const float* pred_w = (const float*)d_in[22];
    const float* pred_b = (const float*)d_in[23];
    const float* Si     = (const float*)d_in[24];
    const float* Zi     = (const float*)d_in[25];

    float* out = (float*)d_out;
    float* out_yhat = out;
    float* out_S    = out + (size_t)NR * MIX3;
    float* out_Z    = out_S + (size_t)NL * NR * NH * HE * HE;

    float *h, *attn, *ffn, *part;
    cudaGetSymbolAddress((void**)&h,    g_h);
    cudaGetSymbolAddress((void**)&attn, g_attn);
    cudaGetSymbolAddress((void**)&ffn,  g_ffn);
    cudaGetSymbolAddress((void**)&part, g_part);

    embed_kernel<<<NR, 256>>>(x, ip, emb, pe);

    const dim3 gQKV(DM / 64, NR / 64, 6);      // 384 blocks (3 outputs x split-K 2)
    const dim3 gWo(DM / 64, NR / 64, 4);       // 256 blocks (split-K 4)
    const dim3 gF1(FF / 64, NR / 64);          // 256 blocks
    const dim3 gF2(DM / 64, NR / 64, 4);       // 256 blocks (split-K 4, chunk 512)
    const dim3 gPred(MIX3 / 64, NR / 64, 4);   // 384 blocks (split-K 4)
    const dim3 gAttn(NR, NH);

    const size_t ssz = (size_t)NR * NH * HE * HE;
    const size_t zsz = (size_t)NR * NH * HE;

    for (int l = 0; l < NL; l++) {
        gemm_qkv_splitk_kernel<<<gQKV, 256>>>(h, Wq, Wk, Wv, part, l);

        attn_kernel<<<gAttn, HE>>>(part, bq, bk, bv, l,
                                   Si + l * ssz, Zi + l * zsz,
                                   out_S + l * ssz, out_Z + l * zsz, attn);

        gemm_splitk_kernel<<<gWo, 256>>>(attn, Wo + (size_t)l * DM * DM, part, DM, DM, 4);
        add_ln_kernel<<<NR, 256>>>(h, part, 4, bo + l * DM, ln1_g + l * DM, ln1_b + l * DM);

        gemm_kernel<2><<<gF1, 256>>>(h, lin1_w + (size_t)l * DM * FF, lin1_b + l * FF,
                                     ffn, FF, DM);
        gemm_splitk_kernel<<<gF2, 256>>>(ffn, lin2_w + (size_t)l * FF * DM, part, DM, FF, 4);
        add_ln_kernel<<<NR, 256>>>(h, part, 4, lin2_b + l * DM, ln2_g + l * DM, ln2_b + l * DM);
    }

    add_ln_kernel<<<NR, 256>>>(h, (const float*)nullptr, 0, (const float*)nullptr, lnf_g, lnf_b);
    gemm_splitk_kernel<<<gPred, 256>>>(h, pred_w, part, MIX3, DM, 4);
    reduce_bias_kernel<<<NR, 256>>>(part, 4, pred_b, out_yhat, MIX3);
}

// round 11
// speedup vs baseline: 1.6557x; 1.2838x over previous
#include <cuda_runtime.h>
#include <math.h>
#include <stdint.h>

// Problem dims
#define NR   512
#define DM   512
#define NH   8
#define HE   64
#define FF   2048
#define NL   6
#define MIX3 768

// ---------------- scratch (device globals; no allocation) ----------------
__device__ __align__(16) float g_h[NR * DM];      // fp32 residual stream
__device__ __align__(16) float g_ht[NR * DM];     // tf32-rounded copy (GEMM A)
__device__ __align__(16) float g_attn[NR * DM];   // rounded (GEMM A only)
__device__ __align__(16) float g_ffn[NR * FF];    // rounded (GEMM A only)
__device__ __align__(16) float g_part[6 * NR * DM];

__device__ __forceinline__ float rtf(float x) {
    unsigned u;
    asm("cvt.rna.tf32.f32 %0, %1;" : "=r"(u) : "f"(x));
    return __uint_as_float(u);
}

// ---------------- embedding + positional concat ----------------
__global__ void embed_kernel(const int* __restrict__ x, const int* __restrict__ ip,
                             const float* __restrict__ emb, const float* __restrict__ pe) {
    int n = blockIdx.x;
    int d = threadIdx.x;
    int tok = x[n];
    int i   = ip[0];
    const float a = emb[tok * 256 + d];
    const float b = pe[i * 256 + d];
    g_h[n * DM + d]        = a;
    g_h[n * DM + 256 + d]  = b;
    g_ht[n * DM + d]       = rtf(a);
    g_ht[n * DM + 256 + d] = rtf(b);
}

// ---------------- TF32 tensor-core GEMM core (cp.async pipelined) ----------
// Tile 64x64, BK=32, 256 threads = 8 warps (2m x 4n), warp tile 32x16.
// A smem: [row][k] 64x32 words, swizzle k' = k ^ ((row&7)<<2). 3 stages (cp.async).
// B smem: [k][n] 32x64 words, swizzle n' = n ^ ((((k<<1)+(n>>5))&7)<<2). 2 buffers.
// A arena must be PRE-ROUNDED to tf32. B rounded inline at STS.

template <int ACT>   // 0 = none (+bias if non-null), 2 = bias+relu+round
__device__ __forceinline__ void gemm_body(
    const float* __restrict__ A, const float* __restrict__ B,
    const float* __restrict__ bias, float* __restrict__ C,
    int N, int K, int kStart, int kEnd, int m0, int n0)
{
    __shared__ __align__(16) float As[3][2048];
    __shared__ __align__(16) float Bs[2][2048];

    const int t    = threadIdx.x;
    const int warp = t >> 5;
    const int lane = t & 31;
    const int g    = lane >> 2;
    const int tg   = lane & 3;
    const int wm   = warp >> 2;       // 0..1 -> m offset 32*wm
    const int wn   = warp & 3;        // 0..3 -> n offset 16*wn

    const int ar  = t >> 2;           // 0..63  A row
    const int ak4 = (t & 3) * 4;      // 0,4,8,12
    const int bk  = t >> 4;           // 0..15  B k row
    const int bn4 = (t & 15) * 4;

    const int nt = (kEnd - kStart) >> 5;   // BK = 32

    const float* Ag = A + (size_t)(m0 + ar) * K + kStart;
    const float* Bg = B + (size_t)(kStart + bk) * N + n0 + bn4;

    const int aw0 = ar * 32 + (ak4 ^ ((ar & 7) << 2));
    const int aw1 = ar * 32 + ((ak4 + 16) ^ ((ar & 7) << 2));
    const uint32_t aS0 = (uint32_t)__cvta_generic_to_shared(&As[0][aw0]);
    const uint32_t aS1 = (uint32_t)__cvta_generic_to_shared(&As[0][aw1]);
    const int bw0 = bk * 64 + (bn4 ^ ((((bk << 1) + (bn4 >> 5)) & 7) << 2));
    const int bw1 = bw0 + 1024;       // (bk+16): XOR term unchanged (32&7==0)

#define LOAD_A(kt, st) do {                                                        \
    const float* _s = Ag + (kt) * 32;                                              \
    asm volatile("cp.async.cg.shared.global [%0], [%1], 16;"                       \
                 :: "r"(aS0 + (uint32_t)(st) * 8192u), "l"(_s + ak4));             \
    asm volatile("cp.async.cg.shared.global [%0], [%1], 16;"                       \
                 :: "r"(aS1 + (uint32_t)(st) * 8192u), "l"(_s + ak4 + 16));        \
} while (0)
#define CP_COMMIT() asm volatile("cp.async.commit_group;")
#define LDG_B(kt, r0, r1) do {                                                     \
    const float* _s = Bg + (size_t)(kt) * 32 * N;                                  \
    r0 = *(const float4*)_s;                                                       \
    r1 = *(const float4*)(_s + (size_t)16 * N);                                    \
} while (0)
#define STS_B(buf, r0, r1) do {                                                    \
    float4 _q0 = make_float4(rtf((r0).x), rtf((r0).y), rtf((r0).z), rtf((r0).w));  \
    float4 _q1 = make_float4(rtf((r1).x), rtf((r1).y), rtf((r1).z), rtf((r1).w));  \
    *(float4*)&Bs[buf][bw0] = _q0;                                                 \
    *(float4*)&Bs[buf][bw1] = _q1;                                                 \
} while (0)

    float c[2][2][4];
#pragma unroll
    for (int i = 0; i < 2; i++)
#pragma unroll
        for (int j = 0; j < 2; j++)
#pragma unroll
            for (int r = 0; r < 4; r++) c[i][j][r] = 0.f;

    // prologue
    float4 b0, b1, p0, p1;
    LDG_B(0, b0, b1);
    STS_B(0, b0, b1);
    if (nt > 1) LDG_B(1, b0, b1);
    LOAD_A(0, 0);
    CP_COMMIT();
    if (nt > 1) LOAD_A(1, 1);
    CP_COMMIT();

    for (int kt = 0; kt < nt; kt++) {
        asm volatile("cp.async.wait_group 1;");
        __syncthreads();

        if (kt + 2 < nt) LOAD_A(kt + 2, (kt + 2) % 3);
        CP_COMMIT();
        const bool pf = (kt + 2 < nt);
        if (pf) LDG_B(kt + 2, p0, p1);

        const float* Ab = &As[kt % 3][0];
        const float* Bb = &Bs[kt & 1][0];

#pragma unroll
        for (int s8 = 0; s8 < 4; s8++) {
            const int kk = s8 * 8;
            unsigned a[2][4], bb[2][2];
            const int kx1 = (kk + tg) ^ (g << 2);
            const int kx2 = (kk + tg + 4) ^ (g << 2);
#pragma unroll
            for (int mt = 0; mt < 2; mt++) {
                const int r0 = (wm * 32 + mt * 16 + g) * 32;
                a[mt][0] = __float_as_uint(Ab[r0 + kx1]);
                a[mt][1] = __float_as_uint(Ab[r0 + 256 + kx1]);   // +8 rows
                a[mt][2] = __float_as_uint(Ab[r0 + kx2]);
                a[mt][3] = __float_as_uint(Ab[r0 + 256 + kx2]);
            }
            const int k1 = kk + tg, k2 = kk + tg + 4;
#pragma unroll
            for (int ntl = 0; ntl < 2; ntl++) {
                const int col = wn * 16 + ntl * 8 + g;
                const int c5 = col >> 5;
                bb[ntl][0] = __float_as_uint(
                    Bb[k1 * 64 + (col ^ ((((k1 << 1) + c5) & 7) << 2))]);
                bb[ntl][1] = __float_as_uint(
                    Bb[k2 * 64 + (col ^ ((((k2 << 1) + c5) & 7) << 2))]);
            }
#pragma unroll
            for (int mt = 0; mt < 2; mt++)
#pragma unroll
                for (int ntl = 0; ntl < 2; ntl++) {
                    asm volatile(
                        "mma.sync.aligned.m16n8k8.row.col.f32.tf32.tf32.f32 "
                        "{%0,%1,%2,%3}, {%4,%5,%6,%7}, {%8,%9}, {%0,%1,%2,%3};"
                        : "+f"(c[mt][ntl][0]), "+f"(c[mt][ntl][1]),
                          "+f"(c[mt][ntl][2]), "+f"(c[mt][ntl][3])
                        : "r"(a[mt][0]), "r"(a[mt][1]), "r"(a[mt][2]), "r"(a[mt][3]),
                          "r"(bb[ntl][0]), "r"(bb[ntl][1]));
                }
        }

        if (kt + 1 < nt) STS_B((kt + 1) & 1, b0, b1);
        b0 = p0; b1 = p1;
    }
#undef LOAD_A
#undef CP_COMMIT
#undef LDG_B
#undef STS_B

    // epilogue: rows g/g+8, cols tg*2, tg*2+1
#pragma unroll
    for (int mt = 0; mt < 2; mt++) {
#pragma unroll
        for (int ntl = 0; ntl < 2; ntl++) {
#pragma unroll
            for (int half = 0; half < 2; half++) {
                const int row = m0 + wm * 32 + mt * 16 + g + half * 8;
                const int col = n0 + wn * 16 + ntl * 8 + tg * 2;
                float v0 = c[mt][ntl][half * 2 + 0];
                float v1 = c[mt][ntl][half * 2 + 1];
                if (bias) { v0 += bias[col]; v1 += bias[col + 1]; }
                if (ACT == 2) {
                    v0 = rtf(fmaxf(v0, 0.f));
                    v1 = rtf(fmaxf(v1, 0.f));
                }
                float2 o = make_float2(v0, v1);
                *(float2*)&C[(size_t)row * N + col] = o;
            }
        }
    }
}

// Plain GEMM (full K); tile 64x64
template <int ACT>
__global__ __launch_bounds__(256, 2) void gemm_kernel(
    const float* __restrict__ A, const float* __restrict__ B,
    const float* __restrict__ bias, float* __restrict__ C, int N, int K)
{
    gemm_body<ACT>(A, B, bias, C, N, K, 0, K, blockIdx.y * 64, blockIdx.x * 64);
}

// Split-K GEMM: partials to Cp + z*NR*N
__global__ __launch_bounds__(256, 2) void gemm_splitk_kernel(
    const float* __restrict__ A, const float* __restrict__ B,
    float* __restrict__ Cp, int N, int K, int S)
{
    const int chunk = K / S;
    const int z = blockIdx.z;
    gemm_body<0>(A, B, nullptr, Cp + (size_t)z * NR * N,
                 N, K, z * chunk, (z + 1) * chunk, blockIdx.y * 64, blockIdx.x * 64);
}

// Fused QKV with split-K 2: z = which*2 + chunk, which: 0=Q 1=K 2=V
__global__ __launch_bounds__(256, 2) void gemm_qkv_splitk_kernel(
    const float* __restrict__ Wq, const float* __restrict__ Wk, const float* __restrict__ Wv,
    float* __restrict__ part, int l)
{
    const int z = blockIdx.z;
    const int which = z >> 1;
    const int chunk = z & 1;
    const float* W = ((which == 0) ? Wq : (which == 1) ? Wk : Wv) + (size_t)l * DM * DM;
    gemm_body<0>(g_ht, W, nullptr, part + (size_t)z * NR * DM,
                 DM, DM, chunk * 256, (chunk + 1) * 256, blockIdx.y * 64, blockIdx.x * 64);
}

// ---------------- split-K reduce + bias (pred head) ----------------
__global__ void reduce_bias_kernel(const float* __restrict__ part, int P,
                                   const float* __restrict__ bias,
                                   float* __restrict__ outp, int N)
{
    const int n = blockIdx.x;
    for (int c = threadIdx.x; c < N; c += blockDim.x) {
        float v = bias[c];
        for (int p = 0; p < P; p++)
            v += part[(size_t)p * NR * N + (size_t)n * N + c];
        outp[(size_t)n * N + c] = v;
    }
}

// ---------------- linear-attention: QKV reduce+bias+phi, state update ------
// part layout: z=0,1 Q partials; 2,3 K partials; 4,5 V partials
__global__ void attn_kernel(const float* __restrict__ part,
                            const float* __restrict__ bq, const float* __restrict__ bk,
                            const float* __restrict__ bv, int l,
                            const float* __restrict__ Si, const float* __restrict__ Zi,
                            float* __restrict__ S_out, float* __restrict__ Z_out)
{
    const int n = blockIdx.x;
    const int h = blockIdx.y;
    const int m = threadIdx.x;

    __shared__ float qs[HE], ks[HE], red[HE];

    const int baseqk = n * DM + h * HE;
    const size_t psz = (size_t)NR * DM;

    float qv = part[baseqk + m] + part[psz + baseqk + m] + bq[l * DM + h * HE + m];
    float kv = part[2 * psz + baseqk + m] + part[3 * psz + baseqk + m] + bk[l * DM + h * HE + m];
    const float vm = part[4 * psz + baseqk + m] + part[5 * psz + baseqk + m] + bv[l * DM + h * HE + m];

    qs[m] = (qv > 0.f) ? (qv + 1.f) : __expf(qv);
    ks[m] = (kv > 0.f) ? (kv + 1.f) : __expf(kv);

    const size_t zbase = ((size_t)n * NH + h) * HE;
    const float z = Zi[zbase + m] + ks[m];
    Z_out[zbase + m] = z;

    red[m] = qs[m] * z;
    __syncthreads();
#pragma unroll
    for (int s = 32; s > 0; s >>= 1) {
        if (m < s) red[m] += red[m + s];
        __syncthreads();
    }
    const float den = red[0] + 1e-6f;

    const size_t sbase = ((size_t)n * NH + h) * HE * HE;
    float num = 0.f;
#pragma unroll 8
    for (int e = 0; e < HE; e++) {
        float s = Si[sbase + (size_t)e * HE + m] + ks[e] * vm;
        S_out[sbase + (size_t)e * HE + m] = s;
        num = fmaf(qs[e], s, num);
    }
    g_attn[baseqk + m] = rtf(num / den);    // GEMM-A arena: pre-rounded
}

// ---------------- residual + split-K reduce + bias + LayerNorm -----------
__global__ void add_ln_kernel(const float* __restrict__ part,
                              int P, const float* __restrict__ bias,
                              const float* __restrict__ g, const float* __restrict__ b)
{
    const int n = blockIdx.x;
    const int t = threadIdx.x;
    __shared__ float red[256];
    __shared__ float s_mean, s_rstd;

    float v0 = g_h[n * DM + t];
    float v1 = g_h[n * DM + 256 + t];
    for (int p = 0; p < P; p++) {
        v0 += part[(size_t)p * NR * DM + n * DM + t];
        v1 += part[(size_t)p * NR * DM + n * DM + 256 + t];
    }
    if (bias) { v0 += bias[t]; v1 += bias[256 + t]; }

    red[t] = v0 + v1;
    __syncthreads();
#pragma unroll
    for (int s = 128; s > 0; s >>= 1) {
        if (t < s) red[t] += red[t + s];
        __syncthreads();
    }
    if (t == 0) s_mean = red[0] * (1.f / DM);
    __syncthreads();
    const float mean = s_mean;

    float d0 = v0 - mean, d1 = v1 - mean;
    red[t] = d0 * d0 + d1 * d1;
    __syncthreads();
#pragma unroll
    for (int s = 128; s > 0; s >>= 1) {
        if (t < s) red[t] += red[t + s];
        __syncthreads();
    }
    if (t == 0) s_rstd = rsqrtf(red[0] * (1.f / DM) + 1e-5f);
    __syncthreads();
    const float rstd = s_rstd;

    const float o0 = d0 * rstd * g[t] + b[t];
    const float o1 = d1 * rstd * g[256 + t] + b[256 + t];
    g_h[n * DM + t]        = o0;
    g_h[n * DM + 256 + t]  = o1;
    g_ht[n * DM + t]       = rtf(o0);
    g_ht[n * DM + 256 + t] = rtf(o1);
}

// ---------------- host-side launch ----------------
extern "C" void kernel_launch(void* const* d_in, const int* in_sizes, int n_in,
                              void* d_out, int out_size)
{
    const int*   x      = (const int*)  d_in[0];
    const int*   ip     = (const int*)  d_in[1];
    const float* emb    = (const float*)d_in[2];
    const float* pe     = (const float*)d_in[3];
    const float* Wq     = (const float*)d_in[4];
    const float* bq     = (const float*)d_in[5];
    const float* Wk     = (const float*)d_in[6];
    const float* bk     = (const float*)d_in[7];
    const float* Wv     = (const float*)d_in[8];
    const float* bv     = (const float*)d_in[9];
    const float* Wo     = (const float*)d_in[10];
    const float* bo     = (const float*)d_in[11];
    const float* ln1_g  = (const float*)d_in[12];
    const float* ln1_b  = (const float*)d_in[13];
    const float* lin1_w = (const float*)d_in[14];
    const float* lin1_b = (const float*)d_in[15];
    const float* lin2_w = (const float*)d_in[16];
    const float* lin2_b = (const float*)d_in[17];
    const float* ln2_g  = (const float*)d_in[18];
    const float* ln2_b  = (const float*)d_in[19];
    const float* lnf_g  = (const float*)d_in[20];
    const float* lnf_b  = (const float*)d_in[21];
    const float* pred_w = (const float*)d_in[22];
    const float* pred_b = (const float*)d_in[23];
    const float* Si     = (const float*)d_in[24];
    const float* Zi     = (const float*)d_in[25];

    float* out = (float*)d_out;
    float* out_yhat = out;
    float* out_S    = out + (size_t)NR * MIX3;
    float* out_Z    = out_S + (size_t)NL * NR * NH * HE * HE;

    float *ht, *attn, *ffn, *part;
    cudaGetSymbolAddress((void**)&ht,   g_ht);
    cudaGetSymbolAddress((void**)&attn, g_attn);
    cudaGetSymbolAddress((void**)&ffn,  g_ffn);
    cudaGetSymbolAddress((void**)&part, g_part);

    embed_kernel<<<NR, 256>>>(x, ip, emb, pe);

    const dim3 gQKV(DM / 64, NR / 64, 6);      // 384 blocks (3 outputs x split-K 2)
    const dim3 gWo(DM / 64, NR / 64, 4);       // 256 blocks (split-K 4)
    const dim3 gF1(FF / 64, NR / 64);          // 256 blocks
    const dim3 gF2(DM / 64, NR / 64, 4);       // 256 blocks (split-K 4, chunk 512)
    const dim3 gPred(MIX3 / 64, NR / 64, 4);   // 384 blocks (split-K 4)
    const dim3 gAttn(NR, NH);

    const size_t ssz = (size_t)NR * NH * HE * HE;
    const size_t zsz = (size_t)NR * NH * HE;

    for (int l = 0; l < NL; l++) {
        gemm_qkv_splitk_kernel<<<gQKV, 256>>>(Wq, Wk, Wv, part, l);

        attn_kernel<<<gAttn, HE>>>(part, bq, bk, bv, l,
                                   Si + l * ssz, Zi + l * zsz,
                                   out_S + l * ssz, out_Z + l * zsz);

        gemm_splitk_kernel<<<gWo, 256>>>(attn, Wo + (size_t)l * DM * DM, part, DM, DM, 4);
        add_ln_kernel<<<NR, 256>>>(part, 4, bo + l * DM, ln1_g + l * DM, ln1_b + l * DM);

        gemm_kernel<2><<<gF1, 256>>>(ht, lin1_w + (size_t)l * DM * FF, lin1_b + l * FF,
                                     ffn, FF, DM);
        gemm_splitk_kernel<<<gF2, 256>>>(ffn, lin2_w + (size_t)l * FF * DM, part, DM, FF, 4);
        add_ln_kernel<<<NR, 256>>>(part, 4, lin2_b + l * DM, ln2_g + l * DM, ln2_b + l * DM);
    }

    add_ln_kernel<<<NR, 256>>>(nullptr, 0, nullptr, lnf_g, lnf_b);
    gemm_splitk_kernel<<<gPred, 256>>>(ht, pred_w, part, MIX3, DM, 4);
    reduce_bias_kernel<<<NR, 256>>>(part, 4, pred_b, out_yhat, MIX3);
}